// round 14
// baseline (speedup 1.0000x reference)
#include <cuda_runtime.h>
#include <math.h>

typedef unsigned long long u64;

#define NB 4
#define NA 256
#define GSZ 12
#define NGR 1728
#define KA 8
#define KG 32
#define NL 4
#define CODE 64
#define HID 128
#define EDGEF 64
#define NGAUSS 20
#define NATOM (NB*NA)          // 1024
#define NGRID (NB*NGR)         // 6912
#define NNODE (NATOM+NGRID)    // 7936
#define MIROWS (2*CODE+EDGEF)  // 192

#define PD_BLOCKS 256
#define PS_BLOCKS 40
#define EDGE_BLOCKS 888
#define NEDGE (NATOM*KA + NGRID*KG)   // 229376

#define NBINS 2048
#define EPB ((NEDGE + 127) / 128)     // edge-prep blocks (1792)
#define TCHUNKS 128                   // 128 chunks of 16 bins

// ---------------- static device scratch ----------------
__device__ float g_h[2][NNODE*CODE];
__device__ float g_npos[NNODE*3];
__device__ int   g_nbrA[NATOM][KA];
__device__ int   g_nbrG[NGRID][KG];
__device__ int4  g_edA[NATOM*KA];       // {nbr*64, bin*64, frac bits, 0}
__device__ int4  g_edG[NGRID*KG];
__device__ float g_Psrc[NATOM*HID];
__device__ float g_Pdst[NNODE*HID];
__device__ float g_EW1[NL][NGAUSS*HID];
__device__ float g_b1eff[NL][HID];
__device__ ulonglong2 g_T2[NL][NBINS*64];   // interleaved {row b, row b+1} pairs
__device__ float4 g_W2q[NL][32*CODE];

struct GaussC { float off[NGAUSS]; float coeff2[NGAUSS]; };

// ---------------- f32x2 helpers ----------------
__device__ __forceinline__ void ffma2(u64 &d, u64 a, u64 b) {
    asm("fma.rn.f32x2 %0, %1, %2, %0;" : "+l"(d) : "l"(a), "l"(b));
}
__device__ __forceinline__ u64 add2(u64 a, u64 b) {
    u64 r; asm("add.rn.f32x2 %0, %1, %2;" : "=l"(r) : "l"(a), "l"(b)); return r;
}
__device__ __forceinline__ u64 pk(float x, float y) {
    u64 r; asm("mov.b64 %0, {%1, %2};" : "=l"(r) : "f"(x), "f"(y)); return r;
}
__device__ __forceinline__ float2 upk(u64 v) {
    float2 r; asm("mov.b64 {%0, %1}, %2;" : "=f"(r.x), "=f"(r.y) : "l"(v)); return r;
}
__device__ __forceinline__ void barhalf(int id) {
    asm volatile("bar.sync %0, %1;" :: "r"(id), "r"(64) : "memory");
}

// ================= k_setup: init + knn_a + knn_g + weight folding =================
__global__ void __launch_bounds__(128) k_setup(
    const float* __restrict__ pos, const int* __restrict__ atype,
    const float* __restrict__ edge_W, const float* __restrict__ edge_b,
    const float* __restrict__ W1, const float* __restrict__ b1,
    const float* __restrict__ W2)
{
    __shared__ float sx[NA], sy[NA], sz[NA];
    int bid = blockIdx.x, t = threadIdx.x;

    if (bid < 248) {
        for (int i = bid * 128 + t; i < NNODE * CODE; i += 248 * 128) {
            int n = i >> 6, c = i & 63;
            g_h[0][i] = (n < NATOM && c == atype[n]) ? 1.f : 0.f;
        }
        for (int i = bid * 128 + t; i < NNODE; i += 248 * 128) {
            float x, y, z;
            if (i < NATOM) { x = pos[i*3]; y = pos[i*3+1]; z = pos[i*3+2]; }
            else {
                int g = (i - NATOM) % NGR;
                int ix = g / (GSZ*GSZ), iy = (g / GSZ) % GSZ, iz = g % GSZ;
                x = -8.25f + 1.5f*ix; y = -8.25f + 1.5f*iy; z = -8.25f + 1.5f*iz;
            }
            g_npos[i*3] = x; g_npos[i*3+1] = y; g_npos[i*3+2] = z;
        }
    } else if (bid < 248 + 256) {
        // ---- atom kNN (warp per node, stable ties) ----
        int abid = bid - 248;
        int lane = t & 31, w = t >> 5;
        int b = (abid * 4) / NA;
        for (int j = t; j < NA; j += 128) {
            int gj = b * NA + j;
            sx[j] = pos[gj*3]; sy[j] = pos[gj*3+1]; sz[j] = pos[gj*3+2];
        }
        __syncthreads();
        int il = (abid * 4 + w) % NA;
        float px = sx[il], py = sy[il], pz = sz[il];
        float d[8];
#pragma unroll
        for (int q = 0; q < 8; q++) {
            int j = q * 32 + lane;
            float dx = sx[j]-px, dy = sy[j]-py, dz = sz[j]-pz;
            float dd = dx*dx + dy*dy + dz*dz;
            d[q] = (j == il) ? 1e30f : dd;
        }
        int keep = 0;
        for (int r = 0; r < KA; r++) {
            float mv = d[0]; int mq = 0;
#pragma unroll
            for (int q = 1; q < 8; q++) if (d[q] < mv) { mv = d[q]; mq = q; }
            int mj = mq * 32 + lane;
#pragma unroll
            for (int off = 16; off; off >>= 1) {
                float ov = __shfl_xor_sync(0xffffffffu, mv, off);
                int   oj = __shfl_xor_sync(0xffffffffu, mj, off);
                if (ov < mv || (ov == mv && oj < mj)) { mv = ov; mj = oj; }
            }
            if (lane == r) keep = mj;
            if ((mj & 31) == lane) {
                int q = mj >> 5;
#pragma unroll
                for (int qq = 0; qq < 8; qq++) if (qq == q) d[qq] = 1e30f;
            }
        }
        if (lane < KA) g_nbrA[b * NA + il][lane] = b * NA + keep;
    } else if (bid < 248 + 256 + 1728) {
        // ---- grid kNN ----
        int gbid = bid - 504;
        int lane = t & 31, w = t >> 5;
        int b = (gbid * 4) / NGR;
        for (int j = t; j < NA; j += 128) {
            int gj = b * NA + j;
            sx[j] = pos[gj*3]; sy[j] = pos[gj*3+1]; sz[j] = pos[gj*3+2];
        }
        __syncthreads();
        int gl = (gbid * 4 + w) % NGR;
        int ix = gl / (GSZ*GSZ), iy = (gl / GSZ) % GSZ, iz = gl % GSZ;
        float px = -8.25f + 1.5f*ix, py = -8.25f + 1.5f*iy, pz = -8.25f + 1.5f*iz;
        float d[8];
#pragma unroll
        for (int q = 0; q < 8; q++) {
            int j = q * 32 + lane;
            float dx = sx[j]-px, dy = sy[j]-py, dz = sz[j]-pz;
            d[q] = dx*dx + dy*dy + dz*dz;
        }
        int keep = 0;
        for (int r = 0; r < KG; r++) {
            float mv = d[0]; int mq = 0;
#pragma unroll
            for (int q = 1; q < 8; q++) if (d[q] < mv) { mv = d[q]; mq = q; }
            int mj = mq * 32 + lane;
#pragma unroll
            for (int off = 16; off; off >>= 1) {
                float ov = __shfl_xor_sync(0xffffffffu, mv, off);
                int   oj = __shfl_xor_sync(0xffffffffu, mj, off);
                if (ov < mv || (ov == mv && oj < mj)) { mv = ov; mj = oj; }
            }
            if (lane == r) keep = mj;
            if ((mj & 31) == lane) {
                int q = mj >> 5;
#pragma unroll
                for (int qq = 0; qq < 8; qq++) if (qq == q) d[qq] = 1e30f;
            }
        }
        g_nbrG[b * NGR + gl][lane] = b * NA + keep;
    } else {
        // ---- weight folding ----
        int pbid = bid - 2232;
        int c = t;
        if (pbid < NL * NGAUSS) {
            int l = pbid / NGAUSS, g = pbid % NGAUSS;
            if (c < EDGEF) sx[c] = edge_W[(l * NGAUSS + g) * EDGEF + c];
            __syncthreads();
            const float* W1c = W1 + l * MIROWS * HID + 2 * CODE * HID;
            float acc = 0.f;
#pragma unroll
            for (int e = 0; e < EDGEF; e++) acc = fmaf(sx[e], W1c[e * HID + c], acc);
            g_EW1[l][g * HID + c] = acc;
        } else if (pbid < NL * NGAUSS + NL) {
            int l = pbid - NL * NGAUSS;
            if (c < EDGEF) sx[c] = edge_b[l * EDGEF + c];
            __syncthreads();
            const float* W1c = W1 + l * MIROWS * HID + 2 * CODE * HID;
            float acc = b1[l * HID + c];
#pragma unroll
            for (int e = 0; e < EDGEF; e++) acc = fmaf(sx[e], W1c[e * HID + c], acc);
            g_b1eff[l][c] = acc;
        } else {
            int l = pbid - NL * NGAUSS - NL;
            const float* W2l = W2 + l * HID * CODE;
            for (int idx = c; idx < 32 * CODE; idx += 128) {
                int k4 = idx / CODE, cc = idx % CODE;
                g_W2q[l][idx] = make_float4(W2l[(4*k4+0)*CODE + cc], W2l[(4*k4+1)*CODE + cc],
                                            W2l[(4*k4+2)*CODE + cc], W2l[(4*k4+3)*CODE + cc]);
            }
        }
    }
}

// ================= k_prep2: edge records (premultiplied) + interleaved tables =================
__global__ void __launch_bounds__(128) k_prep2(GaussC gc) {
    int bid = blockIdx.x, t = threadIdx.x;
    if (bid < EPB) {
        int tid = bid * 128 + t;
        if (tid >= NEDGE) return;
        int node, nbr;
        int4* dst;
        if (tid < NATOM * KA) {
            node = tid / KA;
            nbr = g_nbrA[node][tid % KA];
            dst = &g_edA[tid];
        } else {
            int e = tid - NATOM * KA;
            node = NATOM + e / KG;
            nbr = g_nbrG[e / KG][e % KG];
            dst = &g_edG[e];
        }
        float dx = g_npos[nbr*3]   - g_npos[node*3];
        float dy = g_npos[nbr*3+1] - g_npos[node*3+1];
        float dz = g_npos[nbr*3+2] - g_npos[node*3+2];
        float dist = fminf(sqrtf(dx*dx + dy*dy + dz*dz), 5.0f);
        float x = dist * ((float)NBINS / 5.0f);
        int bin = min((int)x, NBINS - 1);
        float fr = x - (float)bin;
        *dst = make_int4(nbr * 64, bin * 64, __float_as_int(fr), 0);
    } else {
        int tb = bid - EPB;
        int l = tb / TCHUNKS, chunk = tb % TCHUNKS;
        int b0 = chunk * 16;
        __shared__ float sg[17 * NGAUSS];
        for (int i = t; i < 17 * NGAUSS; i += 128) {
            int bb = b0 + i / NGAUSS;
            int g = i % NGAUSS;
            float d = (float)bb * (5.0f / (float)NBINS);
            float dd = d - gc.off[g];
            sg[i] = exp2f(gc.coeff2[g] * dd * dd);
        }
        __syncthreads();
        float ew[NGAUSS];
#pragma unroll
        for (int g = 0; g < NGAUSS; g++) ew[g] = g_EW1[l][g * HID + t];
        float* base = (float*)g_T2[l];
        int c = t >> 1, lohi = t & 1;
        float accPrev = 0.f;
#pragma unroll
        for (int g = 0; g < NGAUSS; g++) accPrev = fmaf(sg[g], ew[g], accPrev);
        for (int bi = 0; bi < 16; bi++) {
            float accNext = 0.f;
            const float* sgr = sg + (bi + 1) * NGAUSS;
#pragma unroll
            for (int g = 0; g < NGAUSS; g++) accNext = fmaf(sgr[g], ew[g], accNext);
            int pi = ((b0 + bi) * 64 + c) * 4 + lohi;
            base[pi]     = accPrev;
            base[pi + 2] = accNext;
            accPrev = accNext;
        }
    }
}

// ================= k_proj: f32x2 split-K, 4 nodes/iter =================
__global__ void __launch_bounds__(128) k_proj(const float* __restrict__ W1, int l, int cur, int last) {
    int t = threadIdx.x;
    int kh = t >> 6, cp = t & 63;
    bool srcRole = blockIdx.x >= PD_BLOCKS;
    const float* Wb = W1 + (srcRole ? 0 : CODE * HID);

    // weight pairs: channels (2cp, 2cp+1) for k in [32kh, 32kh+32)
    u64 wp[32];
#pragma unroll
    for (int i = 0; i < 32; i++) {
        const float* row = Wb + (32 * kh + i) * HID + 2 * cp;
        wp[i] = pk(row[0], row[1]);
    }
    u64 bias = srcRole ? 0ull : ((const u64*)g_b1eff[l])[cp];

    float* dst = srcRole ? g_Psrc : g_Pdst;
    int chStart = (!srcRole && last) ? (NATOM / 4) : 0;   // skip atom Pdst in last layer
    int nCh = (srcRole ? NATOM : NNODE) / 4;
    int b0 = chStart + (srcRole ? (blockIdx.x - PD_BLOCKS) : blockIdx.x);
    int nBlk = srcRole ? PS_BLOCKS : PD_BLOCKS;

    __shared__ u64 shd[4][CODE];     // duplicated (h,h) pairs
    __shared__ u64 spart[4][CODE];   // kh=0 partials
    const float* hsrc = g_h[cur];
    u64* dstq = (u64*)dst;

    for (int ch = b0; ch < nCh; ch += nBlk) {
        int n0 = ch * 4;
        float h0 = hsrc[n0 * CODE + t];          // nodes 0,1
        float h1 = hsrc[n0 * CODE + 128 + t];    // nodes 2,3
        shd[t >> 6][t & 63]       = pk(h0, h0);
        shd[2 + (t >> 6)][t & 63] = pk(h1, h1);
        __syncthreads();
        u64 accs[4];
#pragma unroll
        for (int q = 0; q < 4; q++) {
            u64 acc = kh ? 0ull : bias;
            const u64* hp = shd[q] + 32 * kh;
#pragma unroll
            for (int i = 0; i < 32; i++) ffma2(acc, hp[i], wp[i]);
            accs[q] = acc;
            if (kh == 0) spart[q][cp] = acc;
        }
        __syncthreads();
        if (kh == 1) {
#pragma unroll
            for (int q = 0; q < 4; q++)
                dstq[(size_t)(n0 + q) * 64 + cp] = add2(accs[q], spart[q][cp]);
        }
        __syncthreads();
    }
}

// ================= k_edge: 2 nodes per half, compile-time K edge loop =================
__global__ void __launch_bounds__(128, 5) k_edge(
    const float* __restrict__ b2, const float* __restrict__ lng,
    const float* __restrict__ lnb, int l, int cur, int last,
    float* __restrict__ out)
{
    __shared__ int4   sE[2][2][KG];
    __shared__ __align__(16) float sHS[2][2][HID];
    __shared__ float2 sred[2][2][2];   // [half][sub][warp-half]

    int t = threadIdx.x;
    int half = t >> 6, c = t & 63, lane = t & 31, hw = (t >> 5) & 1;
    int barid = 1 + half;

    float b2c = b2[c], gmc = lng[c], bbc = lnb[c];

    int nStart = last ? NATOM : 0;
    int nQuads = (NNODE - nStart) >> 2;
    const u64* psrcq = (const u64*)g_Psrc;
    const u64* pdstq = (const u64*)g_Pdst;
    const float* hcur = g_h[cur];
    const ulonglong2* w2q = (const ulonglong2*)g_W2q[l];
    const ulonglong2* T2q = g_T2[l];

#define EDGE_BATCH(j0, eArr, pdv, hs0, hs1)                                  \
    {                                                                        \
        int4 e[4]; u64 ps[4]; ulonglong2 tt[4];                              \
        _Pragma("unroll")                                                    \
        for (int m = 0; m < 4; m++) e[m] = eArr[j0 + m];                     \
        _Pragma("unroll")                                                    \
        for (int m = 0; m < 4; m++) {                                        \
            ps[m] = psrcq[e[m].x + c];                                       \
            tt[m] = __ldg(&T2q[e[m].y + c]);                                 \
        }                                                                    \
        _Pragma("unroll")                                                    \
        for (int m = 0; m < 4; m++) {                                        \
            float fr = __int_as_float(e[m].z);                               \
            float om = 1.0f - fr;                                            \
            u64 v = 0ull;                                                    \
            ffma2(v, tt[m].x, pk(om, om));                                   \
            ffma2(v, tt[m].y, pk(fr, fr));                                   \
            float2 bb = upk(add2(add2(pdv, ps[m]), v));                      \
            hs0 += fmaxf(bb.x, 0.f);                                         \
            hs1 += fmaxf(bb.y, 0.f);                                         \
        }                                                                    \
    }

    for (int p = blockIdx.x; p < nQuads; p += gridDim.x) {
        int nA = nStart + 4 * p + 2 * half;
        int nB = nA + 1;
        bool atom = nA < NATOM;      // quad is type-uniform
        int k = atom ? KA : KG;

        u64 pdA = pdstq[nA * 64 + c];
        u64 pdB = pdstq[nB * 64 + c];
        float hresA = __ldg(&hcur[nA * CODE + c]);
        float hresB = __ldg(&hcur[nB * CODE + c]);

        if (c < k) {
            if (atom) {
                sE[half][0][c] = g_edA[nA * KA + c];
                sE[half][1][c] = g_edA[nB * KA + c];
            } else {
                sE[half][0][c] = g_edG[(nA - NATOM) * KG + c];
                sE[half][1][c] = g_edG[(nB - NATOM) * KG + c];
            }
        }
        barhalf(barid);                       // (A) edge records ready

        float hsA0 = 0.f, hsA1 = 0.f, hsB0 = 0.f, hsB1 = 0.f;
        const int4* eA_ = sE[half][0];
        const int4* eB_ = sE[half][1];
        if (atom) {
#pragma unroll
            for (int j0 = 0; j0 < KA; j0 += 4) {
                EDGE_BATCH(j0, eA_, pdA, hsA0, hsA1)
                EDGE_BATCH(j0, eB_, pdB, hsB0, hsB1)
            }
        } else {
#pragma unroll 2
            for (int j0 = 0; j0 < KG; j0 += 4) {
                EDGE_BATCH(j0, eA_, pdA, hsA0, hsA1)
                EDGE_BATCH(j0, eB_, pdB, hsB0, hsB1)
            }
        }
        ((float2*)sHS[half][0])[c] = make_float2(hsA0, hsA1);
        ((float2*)sHS[half][1])[c] = make_float2(hsB0, hsB1);
        barhalf(barid);                       // (B) sHS ready

        // ---- stage 2: W2 read once serves BOTH nodes of this half ----
        u64 aA0 = 0ull, aA1 = 0ull, aB0 = 0ull, aB1 = 0ull;
        const ulonglong2* hqA = (const ulonglong2*)sHS[half][0];
        const ulonglong2* hqB = (const ulonglong2*)sHS[half][1];
#pragma unroll 8
        for (int k4 = 0; k4 < 32; k4++) {
            ulonglong2 wv = __ldg(&w2q[k4 * CODE + c]);
            ulonglong2 hA = hqA[k4];
            ulonglong2 hB = hqB[k4];
            ffma2(aA0, hA.x, wv.x);
            ffma2(aA1, hA.y, wv.y);
            ffma2(aB0, hB.x, wv.x);
            ffma2(aB1, hB.y, wv.y);
        }
        float inv = atom ? (1.f / KA) : (1.f / KG);
        float2 pA0 = upk(aA0), pA1 = upk(aA1);
        float2 pB0 = upk(aB0), pB1 = upk(aB1);
        float xA = hresA + (pA0.x + pA0.y + pA1.x + pA1.y) * inv + b2c;
        float xB = hresB + (pB0.x + pB0.y + pB1.x + pB1.y) * inv + b2c;

        // ---- single-pass LN for both nodes ----
        float sA1 = xA, sA2 = xA * xA, sB1 = xB, sB2 = xB * xB;
#pragma unroll
        for (int off = 16; off; off >>= 1) {
            sA1 += __shfl_xor_sync(0xffffffffu, sA1, off);
            sA2 += __shfl_xor_sync(0xffffffffu, sA2, off);
            sB1 += __shfl_xor_sync(0xffffffffu, sB1, off);
            sB2 += __shfl_xor_sync(0xffffffffu, sB2, off);
        }
        if (lane == 0) {
            sred[half][0][hw] = make_float2(sA1, sA2);
            sred[half][1][hw] = make_float2(sB1, sB2);
        }
        barhalf(barid);                       // (C) sred ready
        {
            float2 ra = sred[half][0][0], rb = sred[half][0][1];
            float mu  = (ra.x + rb.x) * (1.f / CODE);
            float var = (ra.y + rb.y) * (1.f / CODE) - mu * mu;
            float y = (xA - mu) * rsqrtf(var + 1e-5f) * gmc + bbc;
            if (last) out[(nA - NATOM) * CODE + c] = y;
            else      g_h[cur ^ 1][nA * CODE + c] = y;
        }
        {
            float2 ra = sred[half][1][0], rb = sred[half][1][1];
            float mu  = (ra.x + rb.x) * (1.f / CODE);
            float var = (ra.y + rb.y) * (1.f / CODE) - mu * mu;
            float y = (xB - mu) * rsqrtf(var + 1e-5f) * gmc + bbc;
            if (last) out[(nB - NATOM) * CODE + c] = y;
            else      g_h[cur ^ 1][nB * CODE + c] = y;
        }
    }
#undef EDGE_BATCH
}

// ---------------- launch ----------------
extern "C" void kernel_launch(void* const* d_in, const int* in_sizes, int n_in,
                              void* d_out, int out_size) {
    const float* pos    = (const float*)d_in[0];
    const int*   atype  = (const int*)  d_in[1];
    const float* edge_W = (const float*)d_in[3];
    const float* edge_b = (const float*)d_in[4];
    const float* W1     = (const float*)d_in[5];
    const float* b1     = (const float*)d_in[6];
    const float* W2     = (const float*)d_in[7];
    const float* b2     = (const float*)d_in[8];
    const float* lng    = (const float*)d_in[9];
    const float* lnb    = (const float*)d_in[10];
    float* out = (float*)d_out;

    GaussC gc;
    {
        double off[NGAUSS], dd[NGAUSS];
        double hi = log(6.0);
        for (int g = 0; g < NGAUSS; g++) off[g] = exp(hi * (double)g / 19.0) - 1.0;
        for (int g = NGAUSS - 1; g >= 1; g--) dd[g] = off[g] - off[g-1];
        dd[0] = dd[1];
        for (int g = 0; g < NGAUSS; g++) {
            double coeff = -0.5 / (dd[g] * dd[g]);
            gc.off[g]    = (float)off[g];
            gc.coeff2[g] = (float)(coeff * 1.4426950408889634);
        }
    }

    k_setup<<<2232 + NL*NGAUSS + 2*NL, 128>>>(pos, atype, edge_W, edge_b, W1, b1, W2);
    k_prep2<<<EPB + NL*TCHUNKS, 128>>>(gc);

    int cur = 0;
    for (int l = 0; l < NL; l++) {
        int last = (l == NL - 1) ? 1 : 0;
        k_proj<<<PD_BLOCKS + PS_BLOCKS, 128>>>(W1 + l*MIROWS*HID, l, cur, last);
        k_edge<<<EDGE_BLOCKS, 128>>>(b2 + l*CODE, lng + l*CODE, lnb + l*CODE,
                                     l, cur, last, out);
        cur ^= 1;
    }
}

// round 15
// speedup vs baseline: 1.0978x; 1.0978x over previous
#include <cuda_runtime.h>
#include <math.h>

typedef unsigned long long u64;

#define NB 4
#define NA 256
#define GSZ 12
#define NGR 1728
#define KA 8
#define KG 32
#define NL 4
#define CODE 64
#define HID 128
#define EDGEF 64
#define NGAUSS 20
#define NATOM (NB*NA)          // 1024
#define NGRID (NB*NGR)         // 6912
#define NNODE (NATOM+NGRID)    // 7936
#define MIROWS (2*CODE+EDGEF)  // 192

#define PD_BLOCKS 256
#define PS_BLOCKS 40
#define EDGE_BLOCKS 1480
#define NEDGE (NATOM*KA + NGRID*KG)   // 229376

#define NBINS 2048
#define EPB ((NEDGE + 127) / 128)     // edge-prep blocks (1792)
#define TCHUNKS 128                   // 128 chunks of 16 bins
#define PD0_BLOCKS 124                // layer-0 Pdst fill (64 nodes each)
#define PS0_BLOCKS 8                  // layer-0 Psrc gather (128 atoms each)

// ---------------- static device scratch ----------------
__device__ float g_h[2][NNODE*CODE];
__device__ float g_npos[NNODE*3];
__device__ int   g_nbrA[NATOM][KA];
__device__ int   g_nbrG[NGRID][KG];
__device__ int4  g_edA[NATOM*KA];       // {nbr*64, bin*64, frac bits, 0}
__device__ int4  g_edG[NGRID*KG];
__device__ float g_Psrc[NATOM*HID];
__device__ float g_Pdst[NNODE*HID];
__device__ float g_EW1[NL][NGAUSS*HID];
__device__ float g_b1eff[NL][HID];
__device__ ulonglong2 g_T2[NL][NBINS*64];   // interleaved {row b, row b+1} pairs
__device__ float4 g_W2q[NL][32*CODE];

struct GaussC { float off[NGAUSS]; float coeff2[NGAUSS]; };

// ---------------- f32x2 helpers ----------------
__device__ __forceinline__ void ffma2(u64 &d, u64 a, u64 b) {
    asm("fma.rn.f32x2 %0, %1, %2, %0;" : "+l"(d) : "l"(a), "l"(b));
}
__device__ __forceinline__ u64 add2(u64 a, u64 b) {
    u64 r; asm("add.rn.f32x2 %0, %1, %2;" : "=l"(r) : "l"(a), "l"(b)); return r;
}
__device__ __forceinline__ u64 pk(float x, float y) {
    u64 r; asm("mov.b64 %0, {%1, %2};" : "=l"(r) : "f"(x), "f"(y)); return r;
}
__device__ __forceinline__ float2 upk(u64 v) {
    float2 r; asm("mov.b64 {%0, %1}, %2;" : "=f"(r.x), "=f"(r.y) : "l"(v)); return r;
}
__device__ __forceinline__ void barhalf(int id) {
    asm volatile("bar.sync %0, %1;" :: "r"(id), "r"(64) : "memory");
}

// ================= k_setup: init + knn_a + knn_g + weight folding =================
__global__ void __launch_bounds__(128) k_setup(
    const float* __restrict__ pos, const int* __restrict__ atype,
    const float* __restrict__ edge_W, const float* __restrict__ edge_b,
    const float* __restrict__ W1, const float* __restrict__ b1,
    const float* __restrict__ W2)
{
    __shared__ float sx[NA], sy[NA], sz[NA];
    int bid = blockIdx.x, t = threadIdx.x;

    if (bid < 248) {
        for (int i = bid * 128 + t; i < NNODE * CODE; i += 248 * 128) {
            int n = i >> 6, c = i & 63;
            g_h[0][i] = (n < NATOM && c == atype[n]) ? 1.f : 0.f;
        }
        for (int i = bid * 128 + t; i < NNODE; i += 248 * 128) {
            float x, y, z;
            if (i < NATOM) { x = pos[i*3]; y = pos[i*3+1]; z = pos[i*3+2]; }
            else {
                int g = (i - NATOM) % NGR;
                int ix = g / (GSZ*GSZ), iy = (g / GSZ) % GSZ, iz = g % GSZ;
                x = -8.25f + 1.5f*ix; y = -8.25f + 1.5f*iy; z = -8.25f + 1.5f*iz;
            }
            g_npos[i*3] = x; g_npos[i*3+1] = y; g_npos[i*3+2] = z;
        }
    } else if (bid < 248 + 256) {
        // ---- atom kNN (warp per node, stable ties) ----
        int abid = bid - 248;
        int lane = t & 31, w = t >> 5;
        int b = (abid * 4) / NA;
        for (int j = t; j < NA; j += 128) {
            int gj = b * NA + j;
            sx[j] = pos[gj*3]; sy[j] = pos[gj*3+1]; sz[j] = pos[gj*3+2];
        }
        __syncthreads();
        int il = (abid * 4 + w) % NA;
        float px = sx[il], py = sy[il], pz = sz[il];
        float d[8];
#pragma unroll
        for (int q = 0; q < 8; q++) {
            int j = q * 32 + lane;
            float dx = sx[j]-px, dy = sy[j]-py, dz = sz[j]-pz;
            float dd = dx*dx + dy*dy + dz*dz;
            d[q] = (j == il) ? 1e30f : dd;
        }
        int keep = 0;
        for (int r = 0; r < KA; r++) {
            float mv = d[0]; int mq = 0;
#pragma unroll
            for (int q = 1; q < 8; q++) if (d[q] < mv) { mv = d[q]; mq = q; }
            int mj = mq * 32 + lane;
#pragma unroll
            for (int off = 16; off; off >>= 1) {
                float ov = __shfl_xor_sync(0xffffffffu, mv, off);
                int   oj = __shfl_xor_sync(0xffffffffu, mj, off);
                if (ov < mv || (ov == mv && oj < mj)) { mv = ov; mj = oj; }
            }
            if (lane == r) keep = mj;
            if ((mj & 31) == lane) {
                int q = mj >> 5;
#pragma unroll
                for (int qq = 0; qq < 8; qq++) if (qq == q) d[qq] = 1e30f;
            }
        }
        if (lane < KA) g_nbrA[b * NA + il][lane] = b * NA + keep;
    } else if (bid < 248 + 256 + 1728) {
        // ---- grid kNN ----
        int gbid = bid - 504;
        int lane = t & 31, w = t >> 5;
        int b = (gbid * 4) / NGR;
        for (int j = t; j < NA; j += 128) {
            int gj = b * NA + j;
            sx[j] = pos[gj*3]; sy[j] = pos[gj*3+1]; sz[j] = pos[gj*3+2];
        }
        __syncthreads();
        int gl = (gbid * 4 + w) % NGR;
        int ix = gl / (GSZ*GSZ), iy = (gl / GSZ) % GSZ, iz = gl % GSZ;
        float px = -8.25f + 1.5f*ix, py = -8.25f + 1.5f*iy, pz = -8.25f + 1.5f*iz;
        float d[8];
#pragma unroll
        for (int q = 0; q < 8; q++) {
            int j = q * 32 + lane;
            float dx = sx[j]-px, dy = sy[j]-py, dz = sz[j]-pz;
            d[q] = dx*dx + dy*dy + dz*dz;
        }
        int keep = 0;
        for (int r = 0; r < KG; r++) {
            float mv = d[0]; int mq = 0;
#pragma unroll
            for (int q = 1; q < 8; q++) if (d[q] < mv) { mv = d[q]; mq = q; }
            int mj = mq * 32 + lane;
#pragma unroll
            for (int off = 16; off; off >>= 1) {
                float ov = __shfl_xor_sync(0xffffffffu, mv, off);
                int   oj = __shfl_xor_sync(0xffffffffu, mj, off);
                if (ov < mv || (ov == mv && oj < mj)) { mv = ov; mj = oj; }
            }
            if (lane == r) keep = mj;
            if ((mj & 31) == lane) {
                int q = mj >> 5;
#pragma unroll
                for (int qq = 0; qq < 8; qq++) if (qq == q) d[qq] = 1e30f;
            }
        }
        g_nbrG[b * NGR + gl][lane] = b * NA + keep;
    } else {
        // ---- weight folding ----
        int pbid = bid - 2232;
        int c = t;
        if (pbid < NL * NGAUSS) {
            int l = pbid / NGAUSS, g = pbid % NGAUSS;
            if (c < EDGEF) sx[c] = edge_W[(l * NGAUSS + g) * EDGEF + c];
            __syncthreads();
            const float* W1c = W1 + l * MIROWS * HID + 2 * CODE * HID;
            float acc = 0.f;
#pragma unroll
            for (int e = 0; e < EDGEF; e++) acc = fmaf(sx[e], W1c[e * HID + c], acc);
            g_EW1[l][g * HID + c] = acc;
        } else if (pbid < NL * NGAUSS + NL) {
            int l = pbid - NL * NGAUSS;
            if (c < EDGEF) sx[c] = edge_b[l * EDGEF + c];
            __syncthreads();
            const float* W1c = W1 + l * MIROWS * HID + 2 * CODE * HID;
            float acc = b1[l * HID + c];
#pragma unroll
            for (int e = 0; e < EDGEF; e++) acc = fmaf(sx[e], W1c[e * HID + c], acc);
            g_b1eff[l][c] = acc;
        } else {
            int l = pbid - NL * NGAUSS - NL;
            const float* W2l = W2 + l * HID * CODE;
            for (int idx = c; idx < 32 * CODE; idx += 128) {
                int k4 = idx / CODE, cc = idx % CODE;
                g_W2q[l][idx] = make_float4(W2l[(4*k4+0)*CODE + cc], W2l[(4*k4+1)*CODE + cc],
                                            W2l[(4*k4+2)*CODE + cc], W2l[(4*k4+3)*CODE + cc]);
            }
        }
    }
}

// ================= k_prep2: edge records + tables + layer-0 proj (LUT) =================
__global__ void __launch_bounds__(128) k_prep2(GaussC gc, const float* __restrict__ W1,
                                               const int* __restrict__ atype) {
    int bid = blockIdx.x, t = threadIdx.x;
    if (bid < EPB) {
        int tid = bid * 128 + t;
        if (tid >= NEDGE) return;
        int node, nbr;
        int4* dst;
        if (tid < NATOM * KA) {
            node = tid / KA;
            nbr = g_nbrA[node][tid % KA];
            dst = &g_edA[tid];
        } else {
            int e = tid - NATOM * KA;
            node = NATOM + e / KG;
            nbr = g_nbrG[e / KG][e % KG];
            dst = &g_edG[e];
        }
        float dx = g_npos[nbr*3]   - g_npos[node*3];
        float dy = g_npos[nbr*3+1] - g_npos[node*3+1];
        float dz = g_npos[nbr*3+2] - g_npos[node*3+2];
        float dist = fminf(sqrtf(dx*dx + dy*dy + dz*dz), 5.0f);
        float x = dist * ((float)NBINS / 5.0f);
        int bin = min((int)x, NBINS - 1);
        float fr = x - (float)bin;
        *dst = make_int4(nbr * 64, bin * 64, __float_as_int(fr), 0);
    } else if (bid < EPB + NL * TCHUNKS) {
        int tb = bid - EPB;
        int l = tb / TCHUNKS, chunk = tb % TCHUNKS;
        int b0 = chunk * 16;
        __shared__ float sg[17 * NGAUSS];
        for (int i = t; i < 17 * NGAUSS; i += 128) {
            int bb = b0 + i / NGAUSS;
            int g = i % NGAUSS;
            float d = (float)bb * (5.0f / (float)NBINS);
            float dd = d - gc.off[g];
            sg[i] = exp2f(gc.coeff2[g] * dd * dd);
        }
        __syncthreads();
        float ew[NGAUSS];
#pragma unroll
        for (int g = 0; g < NGAUSS; g++) ew[g] = g_EW1[l][g * HID + t];
        float* base = (float*)g_T2[l];
        int c = t >> 1, lohi = t & 1;
        float accPrev = 0.f;
#pragma unroll
        for (int g = 0; g < NGAUSS; g++) accPrev = fmaf(sg[g], ew[g], accPrev);
        for (int bi = 0; bi < 16; bi++) {
            float accNext = 0.f;
            const float* sgr = sg + (bi + 1) * NGAUSS;
#pragma unroll
            for (int g = 0; g < NGAUSS; g++) accNext = fmaf(sgr[g], ew[g], accNext);
            int pi = ((b0 + bi) * 64 + c) * 4 + lohi;
            base[pi]     = accPrev;
            base[pi + 2] = accNext;
            accPrev = accNext;
        }
    } else if (bid < EPB + NL * TCHUNKS + PD0_BLOCKS) {
        // ---- layer-0 Pdst: b1eff (+ W1b[type] for atoms); exact LUT ----
        int pb = bid - EPB - NL * TCHUNKS;
        float bias = g_b1eff[0][t];
        const float* W1b = W1 + CODE * HID;
        int n0 = pb * 64;
        for (int q = 0; q < 64; q++) {
            int n = n0 + q;
            float v = bias;
            if (n < NATOM) v += W1b[atype[n] * HID + t];
            g_Pdst[n * HID + t] = v;
        }
    } else {
        // ---- layer-0 Psrc: W1a[type] for atoms ----
        int pb = bid - EPB - NL * TCHUNKS - PD0_BLOCKS;
        int n0 = pb * 128;
        for (int q = 0; q < 128; q++) {
            int n = n0 + q;
            g_Psrc[n * HID + t] = W1[atype[n] * HID + t];
        }
    }
}

// ================= k_proj: f32x2 split-K, 4 nodes/iter (layers >= 1) =================
__global__ void __launch_bounds__(128) k_proj(const float* __restrict__ W1, int l, int cur, int last) {
    int t = threadIdx.x;
    int kh = t >> 6, cp = t & 63;
    bool srcRole = blockIdx.x >= PD_BLOCKS;
    const float* Wb = W1 + (srcRole ? 0 : CODE * HID);

    u64 wp[32];
#pragma unroll
    for (int i = 0; i < 32; i++) {
        const float* row = Wb + (32 * kh + i) * HID + 2 * cp;
        wp[i] = pk(row[0], row[1]);
    }
    u64 bias = srcRole ? 0ull : ((const u64*)g_b1eff[l])[cp];

    float* dst = srcRole ? g_Psrc : g_Pdst;
    int chStart = (!srcRole && last) ? (NATOM / 4) : 0;
    int nCh = (srcRole ? NATOM : NNODE) / 4;
    int b0 = chStart + (srcRole ? (blockIdx.x - PD_BLOCKS) : blockIdx.x);
    int nBlk = srcRole ? PS_BLOCKS : PD_BLOCKS;

    __shared__ u64 shd[4][CODE];
    __shared__ u64 spart[4][CODE];
    const float* hsrc = g_h[cur];
    u64* dstq = (u64*)dst;

    for (int ch = b0; ch < nCh; ch += nBlk) {
        int n0 = ch * 4;
        float h0 = hsrc[n0 * CODE + t];
        float h1 = hsrc[n0 * CODE + 128 + t];
        shd[t >> 6][t & 63]       = pk(h0, h0);
        shd[2 + (t >> 6)][t & 63] = pk(h1, h1);
        __syncthreads();
        u64 accs[4];
#pragma unroll
        for (int q = 0; q < 4; q++) {
            u64 acc = kh ? 0ull : bias;
            const u64* hp = shd[q] + 32 * kh;
#pragma unroll
            for (int i = 0; i < 32; i++) ffma2(acc, hp[i], wp[i]);
            accs[q] = acc;
            if (kh == 0) spart[q][cp] = acc;
        }
        __syncthreads();
        if (kh == 1) {
#pragma unroll
            for (int q = 0; q < 4; q++)
                dstq[(size_t)(n0 + q) * 64 + cp] = add2(accs[q], spart[q][cp]);
        }
        __syncthreads();
    }
}

// ================= k_edge: 2 nodes per half, compile-time K edge loop =================
__global__ void __launch_bounds__(128, 5) k_edge(
    const float* __restrict__ b2, const float* __restrict__ lng,
    const float* __restrict__ lnb, int l, int cur, int last,
    float* __restrict__ out)
{
    __shared__ int4   sE[2][2][KG];
    __shared__ __align__(16) float sHS[2][2][HID];
    __shared__ float2 sred[2][2][2];   // [half][sub][warp-half]

    int t = threadIdx.x;
    int half = t >> 6, c = t & 63, lane = t & 31, hw = (t >> 5) & 1;
    int barid = 1 + half;

    float b2c = b2[c], gmc = lng[c], bbc = lnb[c];

    int nStart = last ? NATOM : 0;
    int nQuads = (NNODE - nStart) >> 2;
    const u64* psrcq = (const u64*)g_Psrc;
    const u64* pdstq = (const u64*)g_Pdst;
    const float* hcur = g_h[cur];
    const ulonglong2* w2q = (const ulonglong2*)g_W2q[l];
    const ulonglong2* T2q = g_T2[l];

#define EDGE_BATCH(j0, eArr, pdv, hs0, hs1)                                  \
    {                                                                        \
        int4 e[4]; u64 ps[4]; ulonglong2 tt[4];                              \
        _Pragma("unroll")                                                    \
        for (int m = 0; m < 4; m++) e[m] = eArr[j0 + m];                     \
        _Pragma("unroll")                                                    \
        for (int m = 0; m < 4; m++) {                                        \
            ps[m] = psrcq[e[m].x + c];                                       \
            tt[m] = __ldg(&T2q[e[m].y + c]);                                 \
        }                                                                    \
        _Pragma("unroll")                                                    \
        for (int m = 0; m < 4; m++) {                                        \
            float fr = __int_as_float(e[m].z);                               \
            float om = 1.0f - fr;                                            \
            u64 v = 0ull;                                                    \
            ffma2(v, tt[m].x, pk(om, om));                                   \
            ffma2(v, tt[m].y, pk(fr, fr));                                   \
            float2 bb = upk(add2(add2(pdv, ps[m]), v));                      \
            hs0 += fmaxf(bb.x, 0.f);                                         \
            hs1 += fmaxf(bb.y, 0.f);                                         \
        }                                                                    \
    }

    for (int p = blockIdx.x; p < nQuads; p += gridDim.x) {
        int nA = nStart + 4 * p + 2 * half;
        int nB = nA + 1;
        bool atom = nA < NATOM;      // quad is type-uniform
        int k = atom ? KA : KG;

        u64 pdA = pdstq[nA * 64 + c];
        u64 pdB = pdstq[nB * 64 + c];
        float hresA = __ldg(&hcur[nA * CODE + c]);
        float hresB = __ldg(&hcur[nB * CODE + c]);

        if (c < k) {
            if (atom) {
                sE[half][0][c] = g_edA[nA * KA + c];
                sE[half][1][c] = g_edA[nB * KA + c];
            } else {
                sE[half][0][c] = g_edG[(nA - NATOM) * KG + c];
                sE[half][1][c] = g_edG[(nB - NATOM) * KG + c];
            }
        }
        barhalf(barid);                       // (A) edge records ready

        float hsA0 = 0.f, hsA1 = 0.f, hsB0 = 0.f, hsB1 = 0.f;
        const int4* eA_ = sE[half][0];
        const int4* eB_ = sE[half][1];
        if (atom) {
#pragma unroll
            for (int j0 = 0; j0 < KA; j0 += 4) {
                EDGE_BATCH(j0, eA_, pdA, hsA0, hsA1)
                EDGE_BATCH(j0, eB_, pdB, hsB0, hsB1)
            }
        } else {
#pragma unroll 2
            for (int j0 = 0; j0 < KG; j0 += 4) {
                EDGE_BATCH(j0, eA_, pdA, hsA0, hsA1)
                EDGE_BATCH(j0, eB_, pdB, hsB0, hsB1)
            }
        }
        ((float2*)sHS[half][0])[c] = make_float2(hsA0, hsA1);
        ((float2*)sHS[half][1])[c] = make_float2(hsB0, hsB1);
        barhalf(barid);                       // (B) sHS ready

        // ---- stage 2: W2 read once serves BOTH nodes of this half ----
        u64 aA0 = 0ull, aA1 = 0ull, aB0 = 0ull, aB1 = 0ull;
        const ulonglong2* hqA = (const ulonglong2*)sHS[half][0];
        const ulonglong2* hqB = (const ulonglong2*)sHS[half][1];
#pragma unroll 8
        for (int k4 = 0; k4 < 32; k4++) {
            ulonglong2 wv = __ldg(&w2q[k4 * CODE + c]);
            ulonglong2 hA = hqA[k4];
            ulonglong2 hB = hqB[k4];
            ffma2(aA0, hA.x, wv.x);
            ffma2(aA1, hA.y, wv.y);
            ffma2(aB0, hB.x, wv.x);
            ffma2(aB1, hB.y, wv.y);
        }
        float inv = atom ? (1.f / KA) : (1.f / KG);
        float2 pA0 = upk(aA0), pA1 = upk(aA1);
        float2 pB0 = upk(aB0), pB1 = upk(aB1);
        float xA = hresA + (pA0.x + pA0.y + pA1.x + pA1.y) * inv + b2c;
        float xB = hresB + (pB0.x + pB0.y + pB1.x + pB1.y) * inv + b2c;

        // ---- single-pass LN for both nodes ----
        float sA1 = xA, sA2 = xA * xA, sB1 = xB, sB2 = xB * xB;
#pragma unroll
        for (int off = 16; off; off >>= 1) {
            sA1 += __shfl_xor_sync(0xffffffffu, sA1, off);
            sA2 += __shfl_xor_sync(0xffffffffu, sA2, off);
            sB1 += __shfl_xor_sync(0xffffffffu, sB1, off);
            sB2 += __shfl_xor_sync(0xffffffffu, sB2, off);
        }
        if (lane == 0) {
            sred[half][0][hw] = make_float2(sA1, sA2);
            sred[half][1][hw] = make_float2(sB1, sB2);
        }
        barhalf(barid);                       // (C) sred ready
        {
            float2 ra = sred[half][0][0], rb = sred[half][0][1];
            float mu  = (ra.x + rb.x) * (1.f / CODE);
            float var = (ra.y + rb.y) * (1.f / CODE) - mu * mu;
            float y = (xA - mu) * rsqrtf(var + 1e-5f) * gmc + bbc;
            if (last) out[(nA - NATOM) * CODE + c] = y;
            else      g_h[cur ^ 1][nA * CODE + c] = y;
        }
        {
            float2 ra = sred[half][1][0], rb = sred[half][1][1];
            float mu  = (ra.x + rb.x) * (1.f / CODE);
            float var = (ra.y + rb.y) * (1.f / CODE) - mu * mu;
            float y = (xB - mu) * rsqrtf(var + 1e-5f) * gmc + bbc;
            if (last) out[(nB - NATOM) * CODE + c] = y;
            else      g_h[cur ^ 1][nB * CODE + c] = y;
        }
    }
#undef EDGE_BATCH
}

// ---------------- launch ----------------
extern "C" void kernel_launch(void* const* d_in, const int* in_sizes, int n_in,
                              void* d_out, int out_size) {
    const float* pos    = (const float*)d_in[0];
    const int*   atype  = (const int*)  d_in[1];
    const float* edge_W = (const float*)d_in[3];
    const float* edge_b = (const float*)d_in[4];
    const float* W1     = (const float*)d_in[5];
    const float* b1     = (const float*)d_in[6];
    const float* W2     = (const float*)d_in[7];
    const float* b2     = (const float*)d_in[8];
    const float* lng    = (const float*)d_in[9];
    const float* lnb    = (const float*)d_in[10];
    float* out = (float*)d_out;

    GaussC gc;
    {
        double off[NGAUSS], dd[NGAUSS];
        double hi = log(6.0);
        for (int g = 0; g < NGAUSS; g++) off[g] = exp(hi * (double)g / 19.0) - 1.0;
        for (int g = NGAUSS - 1; g >= 1; g--) dd[g] = off[g] - off[g-1];
        dd[0] = dd[1];
        for (int g = 0; g < NGAUSS; g++) {
            double coeff = -0.5 / (dd[g] * dd[g]);
            gc.off[g]    = (float)off[g];
            gc.coeff2[g] = (float)(coeff * 1.4426950408889634);
        }
    }

    k_setup<<<2232 + NL*NGAUSS + 2*NL, 128>>>(pos, atype, edge_W, edge_b, W1, b1, W2);
    k_prep2<<<EPB + NL*TCHUNKS + PD0_BLOCKS + PS0_BLOCKS, 128>>>(gc, W1, atype);

    int cur = 0;
    for (int l = 0; l < NL; l++) {
        int last = (l == NL - 1) ? 1 : 0;
        if (l > 0)
            k_proj<<<PD_BLOCKS + PS_BLOCKS, 128>>>(W1 + l*MIROWS*HID, l, cur, last);
        k_edge<<<EDGE_BLOCKS, 128>>>(b2 + l*CODE, lng + l*CODE, lnb + l*CODE,
                                     l, cur, last, out);
        cur ^= 1;
    }
}

// round 16
// speedup vs baseline: 1.1191x; 1.0194x over previous
#include <cuda_runtime.h>
#include <math.h>

typedef unsigned long long u64;

#define NB 4
#define NA 256
#define GSZ 12
#define NGR 1728
#define KA 8
#define KG 32
#define NL 4
#define CODE 64
#define HID 128
#define EDGEF 64
#define NGAUSS 20
#define NATOM (NB*NA)          // 1024
#define NGRID (NB*NGR)         // 6912
#define NNODE (NATOM+NGRID)    // 7936
#define MIROWS (2*CODE+EDGEF)  // 192

#define PD_BLOCKS 592
#define PS_BLOCKS 148
#define EDGE_BLOCKS 1480
#define NEDGE (NATOM*KA + NGRID*KG)   // 229376

#define NBINS 2048
#define EPB ((NEDGE + 127) / 128)     // edge-prep blocks (1792)
#define TCHUNKS 128                   // 128 chunks of 16 bins
#define PD0_BLOCKS 124                // layer-0 Pdst fill (64 nodes each)
#define PS0_BLOCKS 8                  // layer-0 Psrc gather (128 atoms each)

// ---------------- static device scratch ----------------
__device__ float g_h[2][NNODE*CODE];
__device__ float g_npos[NNODE*3];
__device__ int   g_nbrA[NATOM][KA];
__device__ int   g_nbrG[NGRID][KG];
__device__ int4  g_edA[NATOM*KA];       // {nbr*64, bin*64, frac bits, 0}
__device__ int4  g_edG[NGRID*KG];
__device__ float g_Psrc[NATOM*HID];
__device__ float g_Pdst[NNODE*HID];
__device__ float g_EW1[NL][NGAUSS*HID];
__device__ float g_b1eff[NL][HID];
__device__ ulonglong2 g_T2[NL][NBINS*64];   // interleaved {row b, row b+1} pairs
__device__ float4 g_W2q[NL][32*CODE];

struct GaussC { float off[NGAUSS]; float coeff2[NGAUSS]; };

// ---------------- f32x2 helpers ----------------
__device__ __forceinline__ void ffma2(u64 &d, u64 a, u64 b) {
    asm("fma.rn.f32x2 %0, %1, %2, %0;" : "+l"(d) : "l"(a), "l"(b));
}
__device__ __forceinline__ u64 add2(u64 a, u64 b) {
    u64 r; asm("add.rn.f32x2 %0, %1, %2;" : "=l"(r) : "l"(a), "l"(b)); return r;
}
__device__ __forceinline__ u64 pk(float x, float y) {
    u64 r; asm("mov.b64 %0, {%1, %2};" : "=l"(r) : "f"(x), "f"(y)); return r;
}
__device__ __forceinline__ float2 upk(u64 v) {
    float2 r; asm("mov.b64 {%0, %1}, %2;" : "=f"(r.x), "=f"(r.y) : "l"(v)); return r;
}
__device__ __forceinline__ void barhalf(int id) {
    asm volatile("bar.sync %0, %1;" :: "r"(id), "r"(64) : "memory");
}

// ================= k_setup: init + knn_a + knn_g + weight folding =================
__global__ void __launch_bounds__(128) k_setup(
    const float* __restrict__ pos, const int* __restrict__ atype,
    const float* __restrict__ edge_W, const float* __restrict__ edge_b,
    const float* __restrict__ W1, const float* __restrict__ b1,
    const float* __restrict__ W2)
{
    __shared__ float sx[NA], sy[NA], sz[NA];
    int bid = blockIdx.x, t = threadIdx.x;

    if (bid < 248) {
        for (int i = bid * 128 + t; i < NNODE * CODE; i += 248 * 128) {
            int n = i >> 6, c = i & 63;
            g_h[0][i] = (n < NATOM && c == atype[n]) ? 1.f : 0.f;
        }
        for (int i = bid * 128 + t; i < NNODE; i += 248 * 128) {
            float x, y, z;
            if (i < NATOM) { x = pos[i*3]; y = pos[i*3+1]; z = pos[i*3+2]; }
            else {
                int g = (i - NATOM) % NGR;
                int ix = g / (GSZ*GSZ), iy = (g / GSZ) % GSZ, iz = g % GSZ;
                x = -8.25f + 1.5f*ix; y = -8.25f + 1.5f*iy; z = -8.25f + 1.5f*iz;
            }
            g_npos[i*3] = x; g_npos[i*3+1] = y; g_npos[i*3+2] = z;
        }
    } else if (bid < 248 + 256) {
        // ---- atom kNN (warp per node, stable ties) ----
        int abid = bid - 248;
        int lane = t & 31, w = t >> 5;
        int b = (abid * 4) / NA;
        for (int j = t; j < NA; j += 128) {
            int gj = b * NA + j;
            sx[j] = pos[gj*3]; sy[j] = pos[gj*3+1]; sz[j] = pos[gj*3+2];
        }
        __syncthreads();
        int il = (abid * 4 + w) % NA;
        float px = sx[il], py = sy[il], pz = sz[il];
        float d[8];
#pragma unroll
        for (int q = 0; q < 8; q++) {
            int j = q * 32 + lane;
            float dx = sx[j]-px, dy = sy[j]-py, dz = sz[j]-pz;
            float dd = dx*dx + dy*dy + dz*dz;
            d[q] = (j == il) ? 1e30f : dd;
        }
        int keep = 0;
        for (int r = 0; r < KA; r++) {
            float mv = d[0]; int mq = 0;
#pragma unroll
            for (int q = 1; q < 8; q++) if (d[q] < mv) { mv = d[q]; mq = q; }
            int mj = mq * 32 + lane;
#pragma unroll
            for (int off = 16; off; off >>= 1) {
                float ov = __shfl_xor_sync(0xffffffffu, mv, off);
                int   oj = __shfl_xor_sync(0xffffffffu, mj, off);
                if (ov < mv || (ov == mv && oj < mj)) { mv = ov; mj = oj; }
            }
            if (lane == r) keep = mj;
            if ((mj & 31) == lane) {
                int q = mj >> 5;
#pragma unroll
                for (int qq = 0; qq < 8; qq++) if (qq == q) d[qq] = 1e30f;
            }
        }
        if (lane < KA) g_nbrA[b * NA + il][lane] = b * NA + keep;
    } else if (bid < 248 + 256 + 1728) {
        // ---- grid kNN ----
        int gbid = bid - 504;
        int lane = t & 31, w = t >> 5;
        int b = (gbid * 4) / NGR;
        for (int j = t; j < NA; j += 128) {
            int gj = b * NA + j;
            sx[j] = pos[gj*3]; sy[j] = pos[gj*3+1]; sz[j] = pos[gj*3+2];
        }
        __syncthreads();
        int gl = (gbid * 4 + w) % NGR;
        int ix = gl / (GSZ*GSZ), iy = (gl / GSZ) % GSZ, iz = gl % GSZ;
        float px = -8.25f + 1.5f*ix, py = -8.25f + 1.5f*iy, pz = -8.25f + 1.5f*iz;
        float d[8];
#pragma unroll
        for (int q = 0; q < 8; q++) {
            int j = q * 32 + lane;
            float dx = sx[j]-px, dy = sy[j]-py, dz = sz[j]-pz;
            d[q] = dx*dx + dy*dy + dz*dz;
        }
        int keep = 0;
        for (int r = 0; r < KG; r++) {
            float mv = d[0]; int mq = 0;
#pragma unroll
            for (int q = 1; q < 8; q++) if (d[q] < mv) { mv = d[q]; mq = q; }
            int mj = mq * 32 + lane;
#pragma unroll
            for (int off = 16; off; off >>= 1) {
                float ov = __shfl_xor_sync(0xffffffffu, mv, off);
                int   oj = __shfl_xor_sync(0xffffffffu, mj, off);
                if (ov < mv || (ov == mv && oj < mj)) { mv = ov; mj = oj; }
            }
            if (lane == r) keep = mj;
            if ((mj & 31) == lane) {
                int q = mj >> 5;
#pragma unroll
                for (int qq = 0; qq < 8; qq++) if (qq == q) d[qq] = 1e30f;
            }
        }
        g_nbrG[b * NGR + gl][lane] = b * NA + keep;
    } else {
        // ---- weight folding ----
        int pbid = bid - 2232;
        int c = t;
        if (pbid < NL * NGAUSS) {
            int l = pbid / NGAUSS, g = pbid % NGAUSS;
            if (c < EDGEF) sx[c] = edge_W[(l * NGAUSS + g) * EDGEF + c];
            __syncthreads();
            const float* W1c = W1 + l * MIROWS * HID + 2 * CODE * HID;
            float acc = 0.f;
#pragma unroll
            for (int e = 0; e < EDGEF; e++) acc = fmaf(sx[e], W1c[e * HID + c], acc);
            g_EW1[l][g * HID + c] = acc;
        } else if (pbid < NL * NGAUSS + NL) {
            int l = pbid - NL * NGAUSS;
            if (c < EDGEF) sx[c] = edge_b[l * EDGEF + c];
            __syncthreads();
            const float* W1c = W1 + l * MIROWS * HID + 2 * CODE * HID;
            float acc = b1[l * HID + c];
#pragma unroll
            for (int e = 0; e < EDGEF; e++) acc = fmaf(sx[e], W1c[e * HID + c], acc);
            g_b1eff[l][c] = acc;
        } else {
            int l = pbid - NL * NGAUSS - NL;
            const float* W2l = W2 + l * HID * CODE;
            for (int idx = c; idx < 32 * CODE; idx += 128) {
                int k4 = idx / CODE, cc = idx % CODE;
                g_W2q[l][idx] = make_float4(W2l[(4*k4+0)*CODE + cc], W2l[(4*k4+1)*CODE + cc],
                                            W2l[(4*k4+2)*CODE + cc], W2l[(4*k4+3)*CODE + cc]);
            }
        }
    }
}

// ================= k_prep2: edge records + tables + layer-0 proj (LUT) =================
__global__ void __launch_bounds__(128) k_prep2(GaussC gc, const float* __restrict__ W1,
                                               const int* __restrict__ atype) {
    int bid = blockIdx.x, t = threadIdx.x;
    if (bid < EPB) {
        int tid = bid * 128 + t;
        if (tid >= NEDGE) return;
        int node, nbr;
        int4* dst;
        if (tid < NATOM * KA) {
            node = tid / KA;
            nbr = g_nbrA[node][tid % KA];
            dst = &g_edA[tid];
        } else {
            int e = tid - NATOM * KA;
            node = NATOM + e / KG;
            nbr = g_nbrG[e / KG][e % KG];
            dst = &g_edG[e];
        }
        float dx = g_npos[nbr*3]   - g_npos[node*3];
        float dy = g_npos[nbr*3+1] - g_npos[node*3+1];
        float dz = g_npos[nbr*3+2] - g_npos[node*3+2];
        float dist = fminf(sqrtf(dx*dx + dy*dy + dz*dz), 5.0f);
        float x = dist * ((float)NBINS / 5.0f);
        int bin = min((int)x, NBINS - 1);
        float fr = x - (float)bin;
        *dst = make_int4(nbr * 64, bin * 64, __float_as_int(fr), 0);
    } else if (bid < EPB + NL * TCHUNKS) {
        int tb = bid - EPB;
        int l = tb / TCHUNKS, chunk = tb % TCHUNKS;
        int b0 = chunk * 16;
        __shared__ float sg[17 * NGAUSS];
        for (int i = t; i < 17 * NGAUSS; i += 128) {
            int bb = b0 + i / NGAUSS;
            int g = i % NGAUSS;
            float d = (float)bb * (5.0f / (float)NBINS);
            float dd = d - gc.off[g];
            sg[i] = exp2f(gc.coeff2[g] * dd * dd);
        }
        __syncthreads();
        float ew[NGAUSS];
#pragma unroll
        for (int g = 0; g < NGAUSS; g++) ew[g] = g_EW1[l][g * HID + t];
        float* base = (float*)g_T2[l];
        int c = t >> 1, lohi = t & 1;
        float accPrev = 0.f;
#pragma unroll
        for (int g = 0; g < NGAUSS; g++) accPrev = fmaf(sg[g], ew[g], accPrev);
        for (int bi = 0; bi < 16; bi++) {
            float accNext = 0.f;
            const float* sgr = sg + (bi + 1) * NGAUSS;
#pragma unroll
            for (int g = 0; g < NGAUSS; g++) accNext = fmaf(sgr[g], ew[g], accNext);
            int pi = ((b0 + bi) * 64 + c) * 4 + lohi;
            base[pi]     = accPrev;
            base[pi + 2] = accNext;
            accPrev = accNext;
        }
    } else if (bid < EPB + NL * TCHUNKS + PD0_BLOCKS) {
        // ---- layer-0 Pdst: b1eff (+ W1b[type] for atoms); exact LUT ----
        int pb = bid - EPB - NL * TCHUNKS;
        float bias = g_b1eff[0][t];
        const float* W1b = W1 + CODE * HID;
        int n0 = pb * 64;
        for (int q = 0; q < 64; q++) {
            int n = n0 + q;
            float v = bias;
            if (n < NATOM) v += W1b[atype[n] * HID + t];
            g_Pdst[n * HID + t] = v;
        }
    } else {
        // ---- layer-0 Psrc: W1a[type] for atoms ----
        int pb = bid - EPB - NL * TCHUNKS - PD0_BLOCKS;
        int n0 = pb * 128;
        for (int q = 0; q < 128; q++) {
            int n = n0 + q;
            g_Psrc[n * HID + t] = W1[atype[n] * HID + t];
        }
    }
}

// ================= k_proj: f32x2 split-K, 4 nodes/iter (layers >= 1) =================
__global__ void __launch_bounds__(128) k_proj(const float* __restrict__ W1, int l, int cur, int last) {
    int t = threadIdx.x;
    int kh = t >> 6, cp = t & 63;
    bool srcRole = blockIdx.x >= PD_BLOCKS;
    const float* Wb = W1 + (srcRole ? 0 : CODE * HID);

    u64 wp[32];
#pragma unroll
    for (int i = 0; i < 32; i++) {
        const float* row = Wb + (32 * kh + i) * HID + 2 * cp;
        wp[i] = pk(row[0], row[1]);
    }
    u64 bias = srcRole ? 0ull : ((const u64*)g_b1eff[l])[cp];

    float* dst = srcRole ? g_Psrc : g_Pdst;
    int chStart = (!srcRole && last) ? (NATOM / 4) : 0;
    int nCh = (srcRole ? NATOM : NNODE) / 4;
    int b0 = chStart + (srcRole ? (blockIdx.x - PD_BLOCKS) : blockIdx.x);
    int nBlk = srcRole ? PS_BLOCKS : PD_BLOCKS;

    __shared__ u64 shd[4][CODE];
    __shared__ u64 spart[4][CODE];
    const float* hsrc = g_h[cur];
    u64* dstq = (u64*)dst;

    for (int ch = b0; ch < nCh; ch += nBlk) {
        int n0 = ch * 4;
        float h0 = hsrc[n0 * CODE + t];
        float h1 = hsrc[n0 * CODE + 128 + t];
        shd[t >> 6][t & 63]       = pk(h0, h0);
        shd[2 + (t >> 6)][t & 63] = pk(h1, h1);
        __syncthreads();
        u64 accs[4];
#pragma unroll
        for (int q = 0; q < 4; q++) {
            u64 acc = kh ? 0ull : bias;
            const u64* hp = shd[q] + 32 * kh;
#pragma unroll
            for (int i = 0; i < 32; i++) ffma2(acc, hp[i], wp[i]);
            accs[q] = acc;
            if (kh == 0) spart[q][cp] = acc;
        }
        __syncthreads();
        if (kh == 1) {
#pragma unroll
            for (int q = 0; q < 4; q++)
                dstq[(size_t)(n0 + q) * 64 + cp] = add2(accs[q], spart[q][cp]);
        }
        __syncthreads();
    }
}

// ================= k_edge: 2 nodes per half, compile-time K edge loop =================
__global__ void __launch_bounds__(128, 5) k_edge(
    const float* __restrict__ b2, const float* __restrict__ lng,
    const float* __restrict__ lnb, int l, int cur, int last,
    float* __restrict__ out)
{
    __shared__ int4   sE[2][2][KG];
    __shared__ __align__(16) float sHS[2][2][HID];
    __shared__ float2 sred[2][2][2];   // [half][sub][warp-half]

    int t = threadIdx.x;
    int half = t >> 6, c = t & 63, lane = t & 31, hw = (t >> 5) & 1;
    int barid = 1 + half;

    float b2c = b2[c], gmc = lng[c], bbc = lnb[c];

    int nStart = last ? NATOM : 0;
    int nQuads = (NNODE - nStart) >> 2;
    const u64* psrcq = (const u64*)g_Psrc;
    const u64* pdstq = (const u64*)g_Pdst;
    const float* hcur = g_h[cur];
    const ulonglong2* w2q = (const ulonglong2*)g_W2q[l];
    const ulonglong2* T2q = g_T2[l];

#define EDGE_BATCH(j0, eArr, pdv, hs0, hs1)                                  \
    {                                                                        \
        int4 e[4]; u64 ps[4]; ulonglong2 tt[4];                              \
        _Pragma("unroll")                                                    \
        for (int m = 0; m < 4; m++) e[m] = eArr[j0 + m];                     \
        _Pragma("unroll")                                                    \
        for (int m = 0; m < 4; m++) {                                        \
            ps[m] = psrcq[e[m].x + c];                                       \
            tt[m] = __ldg(&T2q[e[m].y + c]);                                 \
        }                                                                    \
        _Pragma("unroll")                                                    \
        for (int m = 0; m < 4; m++) {                                        \
            float fr = __int_as_float(e[m].z);                               \
            float om = 1.0f - fr;                                            \
            u64 v = 0ull;                                                    \
            ffma2(v, tt[m].x, pk(om, om));                                   \
            ffma2(v, tt[m].y, pk(fr, fr));                                   \
            float2 bb = upk(add2(add2(pdv, ps[m]), v));                      \
            hs0 += fmaxf(bb.x, 0.f);                                         \
            hs1 += fmaxf(bb.y, 0.f);                                         \
        }                                                                    \
    }

    for (int p = blockIdx.x; p < nQuads; p += gridDim.x) {
        int nA = nStart + 4 * p + 2 * half;
        int nB = nA + 1;
        bool atom = nA < NATOM;      // quad is type-uniform
        int k = atom ? KA : KG;

        u64 pdA = pdstq[nA * 64 + c];
        u64 pdB = pdstq[nB * 64 + c];
        float hresA = __ldg(&hcur[nA * CODE + c]);
        float hresB = __ldg(&hcur[nB * CODE + c]);

        if (c < k) {
            if (atom) {
                sE[half][0][c] = g_edA[nA * KA + c];
                sE[half][1][c] = g_edA[nB * KA + c];
            } else {
                sE[half][0][c] = g_edG[(nA - NATOM) * KG + c];
                sE[half][1][c] = g_edG[(nB - NATOM) * KG + c];
            }
        }
        barhalf(barid);                       // (A) edge records ready

        float hsA0 = 0.f, hsA1 = 0.f, hsB0 = 0.f, hsB1 = 0.f;
        const int4* eA_ = sE[half][0];
        const int4* eB_ = sE[half][1];
        if (atom) {
#pragma unroll
            for (int j0 = 0; j0 < KA; j0 += 4) {
                EDGE_BATCH(j0, eA_, pdA, hsA0, hsA1)
                EDGE_BATCH(j0, eB_, pdB, hsB0, hsB1)
            }
        } else {
#pragma unroll 2
            for (int j0 = 0; j0 < KG; j0 += 4) {
                EDGE_BATCH(j0, eA_, pdA, hsA0, hsA1)
                EDGE_BATCH(j0, eB_, pdB, hsB0, hsB1)
            }
        }
        ((float2*)sHS[half][0])[c] = make_float2(hsA0, hsA1);
        ((float2*)sHS[half][1])[c] = make_float2(hsB0, hsB1);
        barhalf(barid);                       // (B) sHS ready

        // ---- stage 2: W2 read once serves BOTH nodes of this half ----
        u64 aA0 = 0ull, aA1 = 0ull, aB0 = 0ull, aB1 = 0ull;
        const ulonglong2* hqA = (const ulonglong2*)sHS[half][0];
        const ulonglong2* hqB = (const ulonglong2*)sHS[half][1];
#pragma unroll 8
        for (int k4 = 0; k4 < 32; k4++) {
            ulonglong2 wv = __ldg(&w2q[k4 * CODE + c]);
            ulonglong2 hA = hqA[k4];
            ulonglong2 hB = hqB[k4];
            ffma2(aA0, hA.x, wv.x);
            ffma2(aA1, hA.y, wv.y);
            ffma2(aB0, hB.x, wv.x);
            ffma2(aB1, hB.y, wv.y);
        }
        float inv = atom ? (1.f / KA) : (1.f / KG);
        float2 pA0 = upk(aA0), pA1 = upk(aA1);
        float2 pB0 = upk(aB0), pB1 = upk(aB1);
        float xA = hresA + (pA0.x + pA0.y + pA1.x + pA1.y) * inv + b2c;
        float xB = hresB + (pB0.x + pB0.y + pB1.x + pB1.y) * inv + b2c;

        // ---- single-pass LN for both nodes ----
        float sA1 = xA, sA2 = xA * xA, sB1 = xB, sB2 = xB * xB;
#pragma unroll
        for (int off = 16; off; off >>= 1) {
            sA1 += __shfl_xor_sync(0xffffffffu, sA1, off);
            sA2 += __shfl_xor_sync(0xffffffffu, sA2, off);
            sB1 += __shfl_xor_sync(0xffffffffu, sB1, off);
            sB2 += __shfl_xor_sync(0xffffffffu, sB2, off);
        }
        if (lane == 0) {
            sred[half][0][hw] = make_float2(sA1, sA2);
            sred[half][1][hw] = make_float2(sB1, sB2);
        }
        barhalf(barid);                       // (C) sred ready
        {
            float2 ra = sred[half][0][0], rb = sred[half][0][1];
            float mu  = (ra.x + rb.x) * (1.f / CODE);
            float var = (ra.y + rb.y) * (1.f / CODE) - mu * mu;
            float y = (xA - mu) * rsqrtf(var + 1e-5f) * gmc + bbc;
            if (last) out[(nA - NATOM) * CODE + c] = y;
            else      g_h[cur ^ 1][nA * CODE + c] = y;
        }
        {
            float2 ra = sred[half][1][0], rb = sred[half][1][1];
            float mu  = (ra.x + rb.x) * (1.f / CODE);
            float var = (ra.y + rb.y) * (1.f / CODE) - mu * mu;
            float y = (xB - mu) * rsqrtf(var + 1e-5f) * gmc + bbc;
            if (last) out[(nB - NATOM) * CODE + c] = y;
            else      g_h[cur ^ 1][nB * CODE + c] = y;
        }
    }
#undef EDGE_BATCH
}

// ---------------- launch ----------------
extern "C" void kernel_launch(void* const* d_in, const int* in_sizes, int n_in,
                              void* d_out, int out_size) {
    const float* pos    = (const float*)d_in[0];
    const int*   atype  = (const int*)  d_in[1];
    const float* edge_W = (const float*)d_in[3];
    const float* edge_b = (const float*)d_in[4];
    const float* W1     = (const float*)d_in[5];
    const float* b1     = (const float*)d_in[6];
    const float* W2     = (const float*)d_in[7];
    const float* b2     = (const float*)d_in[8];
    const float* lng    = (const float*)d_in[9];
    const float* lnb    = (const float*)d_in[10];
    float* out = (float*)d_out;

    GaussC gc;
    {
        double off[NGAUSS], dd[NGAUSS];
        double hi = log(6.0);
        for (int g = 0; g < NGAUSS; g++) off[g] = exp(hi * (double)g / 19.0) - 1.0;
        for (int g = NGAUSS - 1; g >= 1; g--) dd[g] = off[g] - off[g-1];
        dd[0] = dd[1];
        for (int g = 0; g < NGAUSS; g++) {
            double coeff = -0.5 / (dd[g] * dd[g]);
            gc.off[g]    = (float)off[g];
            gc.coeff2[g] = (float)(coeff * 1.4426950408889634);
        }
    }

    k_setup<<<2232 + NL*NGAUSS + 2*NL, 128>>>(pos, atype, edge_W, edge_b, W1, b1, W2);
    k_prep2<<<EPB + NL*TCHUNKS + PD0_BLOCKS + PS0_BLOCKS, 128>>>(gc, W1, atype);

    int cur = 0;
    for (int l = 0; l < NL; l++) {
        int last = (l == NL - 1) ? 1 : 0;
        if (l > 0)
            k_proj<<<PD_BLOCKS + PS_BLOCKS, 128>>>(W1 + l*MIROWS*HID, l, cur, last);
        k_edge<<<EDGE_BLOCKS, 128>>>(b2 + l*CODE, lng + l*CODE, lnb + l*CODE,
                                     l, cur, last, out);
        cur ^= 1;
    }
}

// round 17
// speedup vs baseline: 1.1206x; 1.0013x over previous
#include <cuda_runtime.h>
#include <math.h>

typedef unsigned long long u64;

#define NB 4
#define NA 256
#define GSZ 12
#define NGR 1728
#define KA 8
#define KG 32
#define NL 4
#define CODE 64
#define HID 128
#define EDGEF 64
#define NGAUSS 20
#define NATOM (NB*NA)          // 1024
#define NGRID (NB*NGR)         // 6912
#define NNODE (NATOM+NGRID)    // 7936
#define MIROWS (2*CODE+EDGEF)  // 192

#define PD_BLOCKS 592
#define PS_BLOCKS 128
#define EDGE_BLOCKS 1480
#define NEDGE (NATOM*KA + NGRID*KG)   // 229376

#define NBINS 2048
#define EPB ((NEDGE + 127) / 128)     // edge-prep blocks (1792)
#define TCHUNKS 128                   // 128 chunks of 16 bins
#define PD0_BLOCKS 124                // layer-0 Pdst fill (64 nodes each)
#define PS0_BLOCKS 8                  // layer-0 Psrc gather (128 atoms each)

// ---------------- static device scratch ----------------
__device__ float g_h[2][NNODE*CODE];
__device__ float g_npos[NNODE*3];
__device__ int   g_nbrA[NATOM][KA];
__device__ int   g_nbrG[NGRID][KG];
__device__ int4  g_edA[NATOM*KA];       // {nbr*64, bin*64, frac bits, 0}
__device__ int4  g_edG[NGRID*KG];
__device__ float g_Psrc[NATOM*HID];
__device__ float g_Pdst[NNODE*HID];
__device__ float g_EW1[NL][NGAUSS*HID];
__device__ float g_b1eff[NL][HID];
__device__ ulonglong2 g_T2[NL][NBINS*64];   // interleaved {row b, row b+1} pairs
__device__ float4 g_W2q[NL][32*CODE];

struct GaussC { float off[NGAUSS]; float coeff2[NGAUSS]; };

// ---------------- f32x2 helpers ----------------
__device__ __forceinline__ void ffma2(u64 &d, u64 a, u64 b) {
    asm("fma.rn.f32x2 %0, %1, %2, %0;" : "+l"(d) : "l"(a), "l"(b));
}
__device__ __forceinline__ u64 add2(u64 a, u64 b) {
    u64 r; asm("add.rn.f32x2 %0, %1, %2;" : "=l"(r) : "l"(a), "l"(b)); return r;
}
__device__ __forceinline__ u64 pk(float x, float y) {
    u64 r; asm("mov.b64 %0, {%1, %2};" : "=l"(r) : "f"(x), "f"(y)); return r;
}
__device__ __forceinline__ float2 upk(u64 v) {
    float2 r; asm("mov.b64 {%0, %1}, %2;" : "=f"(r.x), "=f"(r.y) : "l"(v)); return r;
}
__device__ __forceinline__ void barhalf(int id) {
    asm volatile("bar.sync %0, %1;" :: "r"(id), "r"(64) : "memory");
}

// ================= k_setup: init + knn_a + knn_g + weight folding =================
__global__ void __launch_bounds__(128) k_setup(
    const float* __restrict__ pos, const int* __restrict__ atype,
    const float* __restrict__ edge_W, const float* __restrict__ edge_b,
    const float* __restrict__ W1, const float* __restrict__ b1,
    const float* __restrict__ W2)
{
    __shared__ float sx[NA], sy[NA], sz[NA];
    int bid = blockIdx.x, t = threadIdx.x;

    if (bid < 248) {
        for (int i = bid * 128 + t; i < NNODE * CODE; i += 248 * 128) {
            int n = i >> 6, c = i & 63;
            g_h[0][i] = (n < NATOM && c == atype[n]) ? 1.f : 0.f;
        }
        for (int i = bid * 128 + t; i < NNODE; i += 248 * 128) {
            float x, y, z;
            if (i < NATOM) { x = pos[i*3]; y = pos[i*3+1]; z = pos[i*3+2]; }
            else {
                int g = (i - NATOM) % NGR;
                int ix = g / (GSZ*GSZ), iy = (g / GSZ) % GSZ, iz = g % GSZ;
                x = -8.25f + 1.5f*ix; y = -8.25f + 1.5f*iy; z = -8.25f + 1.5f*iz;
            }
            g_npos[i*3] = x; g_npos[i*3+1] = y; g_npos[i*3+2] = z;
        }
    } else if (bid < 248 + 256) {
        // ---- atom kNN (warp per node, stable ties) ----
        int abid = bid - 248;
        int lane = t & 31, w = t >> 5;
        int b = (abid * 4) / NA;
        for (int j = t; j < NA; j += 128) {
            int gj = b * NA + j;
            sx[j] = pos[gj*3]; sy[j] = pos[gj*3+1]; sz[j] = pos[gj*3+2];
        }
        __syncthreads();
        int il = (abid * 4 + w) % NA;
        float px = sx[il], py = sy[il], pz = sz[il];
        float d[8];
#pragma unroll
        for (int q = 0; q < 8; q++) {
            int j = q * 32 + lane;
            float dx = sx[j]-px, dy = sy[j]-py, dz = sz[j]-pz;
            float dd = dx*dx + dy*dy + dz*dz;
            d[q] = (j == il) ? 1e30f : dd;
        }
        int keep = 0;
        for (int r = 0; r < KA; r++) {
            float mv = d[0]; int mq = 0;
#pragma unroll
            for (int q = 1; q < 8; q++) if (d[q] < mv) { mv = d[q]; mq = q; }
            int mj = mq * 32 + lane;
#pragma unroll
            for (int off = 16; off; off >>= 1) {
                float ov = __shfl_xor_sync(0xffffffffu, mv, off);
                int   oj = __shfl_xor_sync(0xffffffffu, mj, off);
                if (ov < mv || (ov == mv && oj < mj)) { mv = ov; mj = oj; }
            }
            if (lane == r) keep = mj;
            if ((mj & 31) == lane) {
                int q = mj >> 5;
#pragma unroll
                for (int qq = 0; qq < 8; qq++) if (qq == q) d[qq] = 1e30f;
            }
        }
        if (lane < KA) g_nbrA[b * NA + il][lane] = b * NA + keep;
    } else if (bid < 248 + 256 + 1728) {
        // ---- grid kNN ----
        int gbid = bid - 504;
        int lane = t & 31, w = t >> 5;
        int b = (gbid * 4) / NGR;
        for (int j = t; j < NA; j += 128) {
            int gj = b * NA + j;
            sx[j] = pos[gj*3]; sy[j] = pos[gj*3+1]; sz[j] = pos[gj*3+2];
        }
        __syncthreads();
        int gl = (gbid * 4 + w) % NGR;
        int ix = gl / (GSZ*GSZ), iy = (gl / GSZ) % GSZ, iz = gl % GSZ;
        float px = -8.25f + 1.5f*ix, py = -8.25f + 1.5f*iy, pz = -8.25f + 1.5f*iz;
        float d[8];
#pragma unroll
        for (int q = 0; q < 8; q++) {
            int j = q * 32 + lane;
            float dx = sx[j]-px, dy = sy[j]-py, dz = sz[j]-pz;
            d[q] = dx*dx + dy*dy + dz*dz;
        }
        int keep = 0;
        for (int r = 0; r < KG; r++) {
            float mv = d[0]; int mq = 0;
#pragma unroll
            for (int q = 1; q < 8; q++) if (d[q] < mv) { mv = d[q]; mq = q; }
            int mj = mq * 32 + lane;
#pragma unroll
            for (int off = 16; off; off >>= 1) {
                float ov = __shfl_xor_sync(0xffffffffu, mv, off);
                int   oj = __shfl_xor_sync(0xffffffffu, mj, off);
                if (ov < mv || (ov == mv && oj < mj)) { mv = ov; mj = oj; }
            }
            if (lane == r) keep = mj;
            if ((mj & 31) == lane) {
                int q = mj >> 5;
#pragma unroll
                for (int qq = 0; qq < 8; qq++) if (qq == q) d[qq] = 1e30f;
            }
        }
        g_nbrG[b * NGR + gl][lane] = b * NA + keep;
    } else {
        // ---- weight folding ----
        int pbid = bid - 2232;
        int c = t;
        if (pbid < NL * NGAUSS) {
            int l = pbid / NGAUSS, g = pbid % NGAUSS;
            if (c < EDGEF) sx[c] = edge_W[(l * NGAUSS + g) * EDGEF + c];
            __syncthreads();
            const float* W1c = W1 + l * MIROWS * HID + 2 * CODE * HID;
            float acc = 0.f;
#pragma unroll
            for (int e = 0; e < EDGEF; e++) acc = fmaf(sx[e], W1c[e * HID + c], acc);
            g_EW1[l][g * HID + c] = acc;
        } else if (pbid < NL * NGAUSS + NL) {
            int l = pbid - NL * NGAUSS;
            if (c < EDGEF) sx[c] = edge_b[l * EDGEF + c];
            __syncthreads();
            const float* W1c = W1 + l * MIROWS * HID + 2 * CODE * HID;
            float acc = b1[l * HID + c];
#pragma unroll
            for (int e = 0; e < EDGEF; e++) acc = fmaf(sx[e], W1c[e * HID + c], acc);
            g_b1eff[l][c] = acc;
        } else {
            int l = pbid - NL * NGAUSS - NL;
            const float* W2l = W2 + l * HID * CODE;
            for (int idx = c; idx < 32 * CODE; idx += 128) {
                int k4 = idx / CODE, cc = idx % CODE;
                g_W2q[l][idx] = make_float4(W2l[(4*k4+0)*CODE + cc], W2l[(4*k4+1)*CODE + cc],
                                            W2l[(4*k4+2)*CODE + cc], W2l[(4*k4+3)*CODE + cc]);
            }
        }
    }
}

// ================= k_prep2: edge records + tables + layer-0 proj (LUT) =================
__global__ void __launch_bounds__(128) k_prep2(GaussC gc, const float* __restrict__ W1,
                                               const int* __restrict__ atype) {
    int bid = blockIdx.x, t = threadIdx.x;
    if (bid < EPB) {
        int tid = bid * 128 + t;
        if (tid >= NEDGE) return;
        int node, nbr;
        int4* dst;
        if (tid < NATOM * KA) {
            node = tid / KA;
            nbr = g_nbrA[node][tid % KA];
            dst = &g_edA[tid];
        } else {
            int e = tid - NATOM * KA;
            node = NATOM + e / KG;
            nbr = g_nbrG[e / KG][e % KG];
            dst = &g_edG[e];
        }
        float dx = g_npos[nbr*3]   - g_npos[node*3];
        float dy = g_npos[nbr*3+1] - g_npos[node*3+1];
        float dz = g_npos[nbr*3+2] - g_npos[node*3+2];
        float dist = fminf(sqrtf(dx*dx + dy*dy + dz*dz), 5.0f);
        float x = dist * ((float)NBINS / 5.0f);
        int bin = min((int)x, NBINS - 1);
        float fr = x - (float)bin;
        *dst = make_int4(nbr * 64, bin * 64, __float_as_int(fr), 0);
    } else if (bid < EPB + NL * TCHUNKS) {
        int tb = bid - EPB;
        int l = tb / TCHUNKS, chunk = tb % TCHUNKS;
        int b0 = chunk * 16;
        __shared__ float sg[17 * NGAUSS];
        for (int i = t; i < 17 * NGAUSS; i += 128) {
            int bb = b0 + i / NGAUSS;
            int g = i % NGAUSS;
            float d = (float)bb * (5.0f / (float)NBINS);
            float dd = d - gc.off[g];
            sg[i] = exp2f(gc.coeff2[g] * dd * dd);
        }
        __syncthreads();
        float ew[NGAUSS];
#pragma unroll
        for (int g = 0; g < NGAUSS; g++) ew[g] = g_EW1[l][g * HID + t];
        float* base = (float*)g_T2[l];
        int c = t >> 1, lohi = t & 1;
        float accPrev = 0.f;
#pragma unroll
        for (int g = 0; g < NGAUSS; g++) accPrev = fmaf(sg[g], ew[g], accPrev);
        for (int bi = 0; bi < 16; bi++) {
            float accNext = 0.f;
            const float* sgr = sg + (bi + 1) * NGAUSS;
#pragma unroll
            for (int g = 0; g < NGAUSS; g++) accNext = fmaf(sgr[g], ew[g], accNext);
            int pi = ((b0 + bi) * 64 + c) * 4 + lohi;
            base[pi]     = accPrev;
            base[pi + 2] = accNext;
            accPrev = accNext;
        }
    } else if (bid < EPB + NL * TCHUNKS + PD0_BLOCKS) {
        // ---- layer-0 Pdst: b1eff (+ W1b[type] for atoms); exact LUT ----
        int pb = bid - EPB - NL * TCHUNKS;
        float bias = g_b1eff[0][t];
        const float* W1b = W1 + CODE * HID;
        int n0 = pb * 64;
        for (int q = 0; q < 64; q++) {
            int n = n0 + q;
            float v = bias;
            if (n < NATOM) v += W1b[atype[n] * HID + t];
            g_Pdst[n * HID + t] = v;
        }
    } else {
        // ---- layer-0 Psrc: W1a[type] for atoms ----
        int pb = bid - EPB - NL * TCHUNKS - PD0_BLOCKS;
        int n0 = pb * 128;
        for (int q = 0; q < 128; q++) {
            int n = n0 + q;
            g_Psrc[n * HID + t] = W1[atype[n] * HID + t];
        }
    }
}

// ================= k_proj: f32x2 split-K, 8 nodes/chunk (layers >= 1) =================
__global__ void __launch_bounds__(128) k_proj(const float* __restrict__ W1, int l, int cur, int last) {
    int t = threadIdx.x;
    int kh = t >> 6, cp = t & 63;
    bool srcRole = blockIdx.x >= PD_BLOCKS;
    const float* Wb = W1 + (srcRole ? 0 : CODE * HID);

    u64 wp[32];
#pragma unroll
    for (int i = 0; i < 32; i++) {
        const float* row = Wb + (32 * kh + i) * HID + 2 * cp;
        wp[i] = pk(row[0], row[1]);
    }
    u64 bias = srcRole ? 0ull : ((const u64*)g_b1eff[l])[cp];

    float* dst = srcRole ? g_Psrc : g_Pdst;
    int chStart = (!srcRole && last) ? (NATOM / 8) : 0;
    int nCh = (srcRole ? NATOM : NNODE) / 8;
    int b0 = chStart + (srcRole ? (blockIdx.x - PD_BLOCKS) : blockIdx.x);
    int nBlk = srcRole ? PS_BLOCKS : PD_BLOCKS;

    __shared__ u64 shd[8][CODE];
    __shared__ u64 spart[8][CODE];
    const float* hsrc = g_h[cur];
    u64* dstq = (u64*)dst;

    for (int ch = b0; ch < nCh; ch += nBlk) {
        int n0 = ch * 8;
        const float* hb = hsrc + (size_t)n0 * CODE;
#pragma unroll
        for (int j = 0; j < 4; j++) {
            int i = t + 128 * j;
            float hv = hb[i];
            shd[i >> 6][i & 63] = pk(hv, hv);
        }
        __syncthreads();
        u64 accs[8];
#pragma unroll
        for (int q = 0; q < 8; q++) {
            u64 acc = kh ? 0ull : bias;
            const u64* hp = shd[q] + 32 * kh;
#pragma unroll
            for (int i = 0; i < 32; i++) ffma2(acc, hp[i], wp[i]);
            accs[q] = acc;
            if (kh == 0) spart[q][cp] = acc;
        }
        __syncthreads();
        if (kh == 1) {
#pragma unroll
            for (int q = 0; q < 8; q++)
                dstq[(size_t)(n0 + q) * 64 + cp] = add2(accs[q], spart[q][cp]);
        }
        __syncthreads();
    }
}

// ================= k_edge: 2 nodes per half, compile-time K edge loop =================
__global__ void __launch_bounds__(128, 5) k_edge(
    const float* __restrict__ b2, const float* __restrict__ lng,
    const float* __restrict__ lnb, int l, int cur, int last,
    float* __restrict__ out)
{
    __shared__ int4   sE[2][2][KG];
    __shared__ __align__(16) float sHS[2][2][HID];
    __shared__ float2 sred[2][2][2];   // [half][sub][warp-half]

    int t = threadIdx.x;
    int half = t >> 6, c = t & 63, lane = t & 31, hw = (t >> 5) & 1;
    int barid = 1 + half;

    float b2c = b2[c], gmc = lng[c], bbc = lnb[c];

    int nStart = last ? NATOM : 0;
    int nQuads = (NNODE - nStart) >> 2;
    const u64* psrcq = (const u64*)g_Psrc;
    const u64* pdstq = (const u64*)g_Pdst;
    const float* hcur = g_h[cur];
    const ulonglong2* w2q = (const ulonglong2*)g_W2q[l];
    const ulonglong2* T2q = g_T2[l];

#define EDGE_BATCH(j0, eArr, pdv, hs0, hs1)                                  \
    {                                                                        \
        int4 e[4]; u64 ps[4]; ulonglong2 tt[4];                              \
        _Pragma("unroll")                                                    \
        for (int m = 0; m < 4; m++) e[m] = eArr[j0 + m];                     \
        _Pragma("unroll")                                                    \
        for (int m = 0; m < 4; m++) {                                        \
            ps[m] = psrcq[e[m].x + c];                                       \
            tt[m] = __ldg(&T2q[e[m].y + c]);                                 \
        }                                                                    \
        _Pragma("unroll")                                                    \
        for (int m = 0; m < 4; m++) {                                        \
            float fr = __int_as_float(e[m].z);                               \
            float om = 1.0f - fr;                                            \
            u64 v = 0ull;                                                    \
            ffma2(v, tt[m].x, pk(om, om));                                   \
            ffma2(v, tt[m].y, pk(fr, fr));                                   \
            float2 bb = upk(add2(add2(pdv, ps[m]), v));                      \
            hs0 += fmaxf(bb.x, 0.f);                                         \
            hs1 += fmaxf(bb.y, 0.f);                                         \
        }                                                                    \
    }

    for (int p = blockIdx.x; p < nQuads; p += gridDim.x) {
        int nA = nStart + 4 * p + 2 * half;
        int nB = nA + 1;
        bool atom = nA < NATOM;      // quad is type-uniform
        int k = atom ? KA : KG;

        u64 pdA = pdstq[nA * 64 + c];
        u64 pdB = pdstq[nB * 64 + c];
        float hresA = __ldg(&hcur[nA * CODE + c]);
        float hresB = __ldg(&hcur[nB * CODE + c]);

        if (c < k) {
            if (atom) {
                sE[half][0][c] = g_edA[nA * KA + c];
                sE[half][1][c] = g_edA[nB * KA + c];
            } else {
                sE[half][0][c] = g_edG[(nA - NATOM) * KG + c];
                sE[half][1][c] = g_edG[(nB - NATOM) * KG + c];
            }
        }
        barhalf(barid);                       // (A) edge records ready

        float hsA0 = 0.f, hsA1 = 0.f, hsB0 = 0.f, hsB1 = 0.f;
        const int4* eA_ = sE[half][0];
        const int4* eB_ = sE[half][1];
        if (atom) {
#pragma unroll
            for (int j0 = 0; j0 < KA; j0 += 4) {
                EDGE_BATCH(j0, eA_, pdA, hsA0, hsA1)
                EDGE_BATCH(j0, eB_, pdB, hsB0, hsB1)
            }
        } else {
#pragma unroll 2
            for (int j0 = 0; j0 < KG; j0 += 4) {
                EDGE_BATCH(j0, eA_, pdA, hsA0, hsA1)
                EDGE_BATCH(j0, eB_, pdB, hsB0, hsB1)
            }
        }
        ((float2*)sHS[half][0])[c] = make_float2(hsA0, hsA1);
        ((float2*)sHS[half][1])[c] = make_float2(hsB0, hsB1);
        barhalf(barid);                       // (B) sHS ready

        // ---- stage 2: W2 read once serves BOTH nodes of this half ----
        u64 aA0 = 0ull, aA1 = 0ull, aB0 = 0ull, aB1 = 0ull;
        const ulonglong2* hqA = (const ulonglong2*)sHS[half][0];
        const ulonglong2* hqB = (const ulonglong2*)sHS[half][1];
#pragma unroll 8
        for (int k4 = 0; k4 < 32; k4++) {
            ulonglong2 wv = __ldg(&w2q[k4 * CODE + c]);
            ulonglong2 hA = hqA[k4];
            ulonglong2 hB = hqB[k4];
            ffma2(aA0, hA.x, wv.x);
            ffma2(aA1, hA.y, wv.y);
            ffma2(aB0, hB.x, wv.x);
            ffma2(aB1, hB.y, wv.y);
        }
        float inv = atom ? (1.f / KA) : (1.f / KG);
        float2 pA0 = upk(aA0), pA1 = upk(aA1);
        float2 pB0 = upk(aB0), pB1 = upk(aB1);
        float xA = hresA + (pA0.x + pA0.y + pA1.x + pA1.y) * inv + b2c;
        float xB = hresB + (pB0.x + pB0.y + pB1.x + pB1.y) * inv + b2c;

        // ---- single-pass LN for both nodes ----
        float sA1 = xA, sA2 = xA * xA, sB1 = xB, sB2 = xB * xB;
#pragma unroll
        for (int off = 16; off; off >>= 1) {
            sA1 += __shfl_xor_sync(0xffffffffu, sA1, off);
            sA2 += __shfl_xor_sync(0xffffffffu, sA2, off);
            sB1 += __shfl_xor_sync(0xffffffffu, sB1, off);
            sB2 += __shfl_xor_sync(0xffffffffu, sB2, off);
        }
        if (lane == 0) {
            sred[half][0][hw] = make_float2(sA1, sA2);
            sred[half][1][hw] = make_float2(sB1, sB2);
        }
        barhalf(barid);                       // (C) sred ready
        {
            float2 ra = sred[half][0][0], rb = sred[half][0][1];
            float mu  = (ra.x + rb.x) * (1.f / CODE);
            float var = (ra.y + rb.y) * (1.f / CODE) - mu * mu;
            float y = (xA - mu) * rsqrtf(var + 1e-5f) * gmc + bbc;
            if (last) out[(nA - NATOM) * CODE + c] = y;
            else      g_h[cur ^ 1][nA * CODE + c] = y;
        }
        {
            float2 ra = sred[half][1][0], rb = sred[half][1][1];
            float mu  = (ra.x + rb.x) * (1.f / CODE);
            float var = (ra.y + rb.y) * (1.f / CODE) - mu * mu;
            float y = (xB - mu) * rsqrtf(var + 1e-5f) * gmc + bbc;
            if (last) out[(nB - NATOM) * CODE + c] = y;
            else      g_h[cur ^ 1][nB * CODE + c] = y;
        }
    }
#undef EDGE_BATCH
}

// ---------------- launch ----------------
extern "C" void kernel_launch(void* const* d_in, const int* in_sizes, int n_in,
                              void* d_out, int out_size) {
    const float* pos    = (const float*)d_in[0];
    const int*   atype  = (const int*)  d_in[1];
    const float* edge_W = (const float*)d_in[3];
    const float* edge_b = (const float*)d_in[4];
    const float* W1     = (const float*)d_in[5];
    const float* b1     = (const float*)d_in[6];
    const float* W2     = (const float*)d_in[7];
    const float* b2     = (const float*)d_in[8];
    const float* lng    = (const float*)d_in[9];
    const float* lnb    = (const float*)d_in[10];
    float* out = (float*)d_out;

    GaussC gc;
    {
        double off[NGAUSS], dd[NGAUSS];
        double hi = log(6.0);
        for (int g = 0; g < NGAUSS; g++) off[g] = exp(hi * (double)g / 19.0) - 1.0;
        for (int g = NGAUSS - 1; g >= 1; g--) dd[g] = off[g] - off[g-1];
        dd[0] = dd[1];
        for (int g = 0; g < NGAUSS; g++) {
            double coeff = -0.5 / (dd[g] * dd[g]);
            gc.off[g]    = (float)off[g];
            gc.coeff2[g] = (float)(coeff * 1.4426950408889634);
        }
    }

    k_setup<<<2232 + NL*NGAUSS + 2*NL, 128>>>(pos, atype, edge_W, edge_b, W1, b1, W2);
    k_prep2<<<EPB + NL*TCHUNKS + PD0_BLOCKS + PS0_BLOCKS, 128>>>(gc, W1, atype);

    int cur = 0;
    for (int l = 0; l < NL; l++) {
        int last = (l == NL - 1) ? 1 : 0;
        if (l > 0)
            k_proj<<<PD_BLOCKS + PS_BLOCKS, 128>>>(W1 + l*MIROWS*HID, l, cur, last);
        k_edge<<<EDGE_BLOCKS, 128>>>(b2 + l*CODE, lng + l*CODE, lnb + l*CODE,
                                     l, cur, last, out);
        cur ^= 1;
    }
}